// round 7
// baseline (speedup 1.0000x reference)
#include <cuda_runtime.h>
#include <math.h>

// ---------------- problem constants ----------------
#define B_    2
#define K_    384
#define N_    4096
#define D_    1024
#define H_    150
#define HP_   152     // padded H
#define HPP_  160     // H padded for MMA K (mult of 8, covers 152)
#define LRWP_ 384     // l|r concatenated row width, padded
#define L_    12
#define NB_   10
#define DE_   20

#define SZ_U   (B_*K_*D_)       // 786432
#define SZ_P   (B_*K_*K_)       // 294912
#define SZ_S   (B_*K_)          // 768

// ---------------- device scratch (static, no allocs) ----------------
__device__ float g_u[SZ_U];        // fp32 u (ping)
__device__ float g_u2[SZ_U];       // fp32 u (pong)
__device__ float g_ut[SZ_U];       // tf32-clean u (ping)
__device__ float g_ut2[SZ_U];      // tf32-clean u (pong)
__device__ float g_lr[B_*K_*LRWP_];
__device__ float g_wlr[D_*LRWP_];  // tf32-clean
__device__ float g_blr[LRWP_];
__device__ float g_dp[NB_*HP_];
__device__ float g_probs[2*SZ_P];  // tf32-clean [probs b0,b1 | probsT b0,b1]
__device__ float g_inv[2*SZ_S];
__device__ float g_c[2*SZ_U];      // tf32-clean [c1 b0,b1 | c2 b0,b1]
__device__ float g_tmp[SZ_U];      // tf32-clean
__device__ float g_ctxt[SZ_U];     // tf32-clean
__device__ float g_wff1t[3*D_*D_]; // tf32-clean weights
__device__ float g_wff2t[D_*D_];
__device__ float g_wgt[2*D_*D_];

__device__ __forceinline__ unsigned f2t(float x) {
    unsigned r;
    asm("cvt.rna.tf32.f32 %0, %1;" : "=r"(r) : "f"(x));
    return r;
}
__device__ __forceinline__ float rna(float x) { return __uint_as_float(f2t(x)); }

__device__ __forceinline__ void cpa16(void* s, const void* g) {
    unsigned sa = (unsigned)__cvta_generic_to_shared(s);
    asm volatile("cp.async.cg.shared.global [%0], [%1], 16;" :: "r"(sa), "l"(g));
}
__device__ __forceinline__ void cp_commit() { asm volatile("cp.async.commit_group;"); }
template<int Nw>
__device__ __forceinline__ void cp_wait() { asm volatile("cp.async.wait_group %0;" :: "n"(Nw)); }

// ---------------- weight/input tf32 conversion (once per launch) ----------------
__global__ void convert_kernel(const float* __restrict__ Wff1,
                               const float* __restrict__ Wff2,
                               const float* __restrict__ Wg,
                               const float* __restrict__ span_vecs,
                               float* __restrict__ wff1t,
                               float* __restrict__ wff2t,
                               float* __restrict__ wgt,
                               float* __restrict__ u,
                               float* __restrict__ ut)
{
    int tid = blockIdx.x * blockDim.x + threadIdx.x;
    int nthr = gridDim.x * blockDim.x;
    for (int i = tid; i < 3*D_*D_; i += nthr) wff1t[i] = rna(Wff1[i]);
    for (int i = tid; i < D_*D_;   i += nthr) wff2t[i] = rna(Wff2[i]);
    for (int i = tid; i < 2*D_*D_; i += nthr) wgt[i]   = rna(Wg[i]);
    for (int i = tid; i < SZ_U; i += nthr) {
        float v = span_vecs[i];
        u[i] = v;
        ut[i] = rna(v);
    }
}

// ---------------- init: dp table + W_lr / b_lr concat (tf32-clean) ----------------
__global__ void init_kernel(const float* __restrict__ dist_emb,
                            const float* __restrict__ Wd,
                            const float* __restrict__ bd,
                            const float* __restrict__ Wl,
                            const float* __restrict__ bl,
                            const float* __restrict__ Wr,
                            const float* __restrict__ br,
                            float* __restrict__ dp,
                            float* __restrict__ wlr,
                            float* __restrict__ blr)
{
    int tid = blockIdx.x * blockDim.x + threadIdx.x;
    int nthr = gridDim.x * blockDim.x;
    for (int idx = tid; idx < NB_*HP_; idx += nthr) {
        int n = idx / HP_, h = idx % HP_;
        float v = 0.f;
        if (h < H_) {
            v = bd[h];
            #pragma unroll
            for (int t = 0; t < DE_; t++)
                v += dist_emb[n * DE_ + t] * Wd[t * H_ + h];
        }
        dp[idx] = v;
    }
    for (int idx = tid; idx < D_*LRWP_; idx += nthr) {
        int k = idx / LRWP_, c = idx % LRWP_;
        float v = 0.f;
        if (c < H_) v = Wl[k * H_ + c];
        else if (c >= HP_ && c < HP_ + H_) v = Wr[k * H_ + (c - HP_)];
        wlr[idx] = rna(v);
    }
    for (int c = tid; c < LRWP_; c += nthr) {
        float v = 0.f;
        if (c < H_) v = bl[c];
        else if (c >= HP_ && c < HP_ + H_) v = br[c - HP_];
        blr[c] = v;
    }
}

// ---------------- tf32 tensor-core GEMM, cp.async 3-stage, single sync/tile ----------------
#define ASTRIDE 36
#define BSTRIDE 72
template<int BM>
__global__ void __launch_bounds__(128, 2)
mma_gemm(const float* __restrict__ a0,
         const float* __restrict__ a1,
         const float* __restrict__ a2,
         const float* __restrict__ W,
         const float* __restrict__ bias,
         const float* __restrict__ rowscale,
         const float* __restrict__ e1,
         const float* __restrict__ e2,
         float* __restrict__ Cout,
         float* __restrict__ Ct,
         int M, int N, int K, int lda, int ldc,
         long sA, long sW, int bzmask, long sC, int sRS,
         int act, int roundOut)
{
    constexpr int MT = BM / 32;
    constexpr int ACH = (BM == 64) ? 4 : 2;
    constexpr int ASZ = BM * ASTRIDE;
    constexpr int BSZ = 32 * BSTRIDE;
    extern __shared__ unsigned dsm[];
    unsigned* Abase = dsm;
    unsigned* Bbase = dsm + 3 * ASZ;

    int z = blockIdx.z;
    a0 += (long)z * sA;
    W  += (long)(z & bzmask) * sW;
    Cout += (long)z * sC;
    if (rowscale) rowscale += (long)z * sRS;

    int tid = threadIdx.x;
    int warp = tid >> 5, lane = tid & 31;
    int m0 = blockIdx.y * BM, n0 = blockIdx.x * 64;
    int wm = (warp >> 1) * (BM / 2), wn = (warp & 1) * 32;

    auto issue = [&](int k0, int stage) {
        unsigned* As = Abase + stage * ASZ;
        unsigned* Bs = Bbase + stage * BSZ;
        int seg = k0 >> 10, col = k0 & 1023;
        const float* ap = (seg == 0) ? a0 : (seg == 1) ? a1 : a2;
        #pragma unroll
        for (int i = 0; i < ACH; i++) {
            int id = tid + i * 128;
            int row = id >> 3, c16 = (id & 7) * 4;
            cpa16(As + row * ASTRIDE + c16, ap + (long)(m0 + row) * lda + col + c16);
        }
        #pragma unroll
        for (int i = 0; i < 4; i++) {
            int id = tid + i * 128;
            int kr = id >> 4, c16 = (id & 15) * 4;
            cpa16(Bs + kr * BSTRIDE + c16, W + (long)(k0 + kr) * N + n0 + c16);
        }
        cp_commit();
    };

    int nt = K >> 5;
    issue(0, 0);
    issue(32, 1);

    float acc[MT][4][4];
    #pragma unroll
    for (int i = 0; i < MT; i++)
        #pragma unroll
        for (int j = 0; j < 4; j++)
            #pragma unroll
            for (int q = 0; q < 4; q++) acc[i][j][q] = 0.f;

    int stage = 0;
    for (int t = 0; t < nt; t++) {
        if (t == nt - 1) cp_wait<0>(); else cp_wait<1>();
        __syncthreads();
        if (t + 2 < nt) issue((t + 2) << 5, (stage + 2) % 3);

        unsigned* As = Abase + stage * ASZ;
        unsigned* Bs = Bbase + stage * BSZ;

        #pragma unroll
        for (int kx = 0; kx < 4; kx++) {
            unsigned a[MT][4];
            #pragma unroll
            for (int mt = 0; mt < MT; mt++) {
                int r_ = wm + mt * 16 + (lane >> 2);
                int c_ = kx * 8 + (lane & 3);
                a[mt][0] = As[r_ * ASTRIDE + c_];
                a[mt][1] = As[(r_ + 8) * ASTRIDE + c_];
                a[mt][2] = As[r_ * ASTRIDE + c_ + 4];
                a[mt][3] = As[(r_ + 8) * ASTRIDE + c_ + 4];
            }
            #pragma unroll
            for (int ct = 0; ct < 4; ct++) {
                unsigned b0 = Bs[(kx*8 + (lane & 3)) * BSTRIDE + wn + ct*8 + (lane >> 2)];
                unsigned b1 = Bs[(kx*8 + (lane & 3) + 4) * BSTRIDE + wn + ct*8 + (lane >> 2)];
                #pragma unroll
                for (int mt = 0; mt < MT; mt++) {
                    asm volatile(
                        "mma.sync.aligned.m16n8k8.row.col.f32.tf32.tf32.f32 "
                        "{%0,%1,%2,%3}, {%4,%5,%6,%7}, {%8,%9}, {%0,%1,%2,%3};"
                        : "+f"(acc[mt][ct][0]), "+f"(acc[mt][ct][1]),
                          "+f"(acc[mt][ct][2]), "+f"(acc[mt][ct][3])
                        : "r"(a[mt][0]), "r"(a[mt][1]), "r"(a[mt][2]), "r"(a[mt][3]),
                          "r"(b0), "r"(b1));
                }
            }
        }
        stage = (stage + 1) % 3;
    }

    #pragma unroll
    for (int mt = 0; mt < MT; mt++) {
        #pragma unroll
        for (int rh = 0; rh < 2; rh++) {
            int gm = m0 + wm + mt * 16 + (lane >> 2) + rh * 8;
            float rs = rowscale ? rowscale[gm] : 1.f;
            #pragma unroll
            for (int ct = 0; ct < 4; ct++) {
                int gn = n0 + wn + ct * 8 + (lane & 3) * 2;
                float v0 = acc[mt][ct][rh * 2 + 0];
                float v1 = acc[mt][ct][rh * 2 + 1];
                if (bias) { v0 += bias[gn]; v1 += bias[gn + 1]; }
                v0 *= rs; v1 *= rs;
                long off = (long)gm * ldc + gn;
                if (act == 1) { v0 = tanhf(v0); v1 = tanhf(v1); }
                else if (act == 2) {
                    v0 = 1.f / (1.f + expf(-v0));
                    v1 = 1.f / (1.f + expf(-v1));
                }
                else if (act == 3) {
                    float g0 = 1.f / (1.f + expf(-v0));
                    float g1 = 1.f / (1.f + expf(-v1));
                    v0 = g0 * e1[off]     + (1.f - g0) * e2[off];
                    v1 = g1 * e1[off + 1] + (1.f - g1) * e2[off + 1];
                }
                if (roundOut) { v0 = rna(v0); v1 = rna(v1); }
                *(float2*)(Cout + off) = make_float2(v0, v1);
                if (Ct) *(float2*)(Ct + off) = make_float2(rna(v0), rna(v1));
            }
        }
    }
}

// ---------------- tensor-core pairwise scorer ----------------
// per block (i, b): scores[b,i,j,:] (+)= relu(t[bucket(j)] + r_j) @ Wo + bo
// via m16n8k8 tf32 MMA: M=32-j tiles, N=16 (12 used), K=160 (152 used).
__global__ void __launch_bounds__(128)
scorer_tc(const float* __restrict__ lr,
          const float* __restrict__ dp,
          const float* __restrict__ Wo,
          const float* __restrict__ bo,
          const int* __restrict__ span_begin,
          const int* __restrict__ span_end,
          float* __restrict__ scores,
          int first)
{
    int i = blockIdx.x, b = blockIdx.y;
    int tid = threadIdx.x;
    int warp = tid >> 5, lane = tid & 31;

    __shared__ float s_t[NB_][HPP_];    // rna(l_i + dp[n]), 0-padded
    __shared__ float s_h[32][164];      // H tile, stride 164 -> conflict-free a-frags
    __shared__ int   s_bk[K_];
    __shared__ float s_bo[16];

    // t table
    const float* lrow = lr + (long)(b * K_ + i) * LRWP_;
    for (int x = tid; x < NB_ * HPP_; x += 128) {
        int n = x / HPP_, h = x % HPP_;
        float v = 0.f;
        if (h < HP_) v = rna(lrow[h] + dp[n * HP_ + h]);
        s_t[n][h] = v;
    }
    // buckets
    int endi = span_end[b * K_ + i];
    for (int j = tid; j < K_; j += 128) {
        int d = span_begin[b * K_ + j] - endi;
        int da = d < 0 ? -d : d;
        int bk;
        if (da <= 4) bk = da;
        else {
            int lg = 31 - __clz(da) + 3;
            bk = lg < (NB_ - 1) ? lg : (NB_ - 1);
        }
        s_bk[j] = bk;
    }
    if (tid < 16) s_bo[tid] = (tid < L_) ? bo[tid] : 0.f;

    // per-warp B fragments (Wo^T) in registers: warp (mtile, ntile)
    int mtile = warp >> 1, ntile = warp & 1;
    int bn = ntile * 8 + (lane >> 2);
    unsigned bw0[20], bw1[20];
    #pragma unroll
    for (int kt = 0; kt < 20; kt++) {
        int k0 = kt * 8 + (lane & 3);
        int k1 = k0 + 4;
        bw0[kt] = (k0 < H_ && bn < L_) ? f2t(Wo[k0 * L_ + bn]) : 0u;
        bw1[kt] = (k1 < H_ && bn < L_) ? f2t(Wo[k1 * L_ + bn]) : 0u;
    }
    __syncthreads();

    const float* rbase = lr + (long)b * K_ * LRWP_ + HP_;
    int jj = tid >> 2;             // 0..31 within tile
    int q  = tid & 3;              // h-quadrant: 40 h's each

    for (int jt = 0; jt < K_ / 32; jt++) {
        // build H tile
        {
            int j = jt * 32 + jj;
            const float* rrow = rbase + (long)j * LRWP_ + q * 40;
            const float* trow = s_t[s_bk[j]] + q * 40;
            float* hrow = &s_h[jj][q * 40];
            #pragma unroll
            for (int x = 0; x < 10; x++) {
                float4 rv = *(const float4*)(rrow + x * 4);
                float4 tv = *(const float4*)(trow + x * 4);
                float4 hv;
                hv.x = rna(fmaxf(rv.x + tv.x, 0.f));
                hv.y = rna(fmaxf(rv.y + tv.y, 0.f));
                hv.z = rna(fmaxf(rv.z + tv.z, 0.f));
                hv.w = rna(fmaxf(rv.w + tv.w, 0.f));
                *(float4*)(hrow + x * 4) = hv;
            }
        }
        __syncthreads();

        // MMA: each warp one 16x8 output tile over K=160
        float acc[4] = {0.f, 0.f, 0.f, 0.f};
        int arow = mtile * 16 + (lane >> 2);
        int acol = lane & 3;
        #pragma unroll
        for (int kt = 0; kt < 20; kt++) {
            unsigned a0 = __float_as_uint(s_h[arow][kt * 8 + acol]);
            unsigned a1 = __float_as_uint(s_h[arow + 8][kt * 8 + acol]);
            unsigned a2 = __float_as_uint(s_h[arow][kt * 8 + acol + 4]);
            unsigned a3 = __float_as_uint(s_h[arow + 8][kt * 8 + acol + 4]);
            asm volatile(
                "mma.sync.aligned.m16n8k8.row.col.f32.tf32.tf32.f32 "
                "{%0,%1,%2,%3}, {%4,%5,%6,%7}, {%8,%9}, {%0,%1,%2,%3};"
                : "+f"(acc[0]), "+f"(acc[1]), "+f"(acc[2]), "+f"(acc[3])
                : "r"(a0), "r"(a1), "r"(a2), "r"(a3), "r"(bw0[kt]), "r"(bw1[kt]));
        }

        // epilogue
        int gc = ntile * 8 + (lane & 3) * 2;
        if (gc < L_) {
            int gj = jt * 32 + mtile * 16 + (lane >> 2);
            long rbofs = ((long)(b * K_ + i) * K_ + gj) * L_ + gc;
            float v0 = acc[0] + s_bo[gc];
            float v1 = acc[1] + s_bo[gc + 1];
            float v2 = acc[2] + s_bo[gc];
            float v3 = acc[3] + s_bo[gc + 1];
            float* o0 = scores + rbofs;
            float* o1 = scores + rbofs + 8 * L_;
            if (!first) {
                float2 p0 = *(float2*)o0, p1 = *(float2*)o1;
                v0 += p0.x; v1 += p0.y; v2 += p1.x; v3 += p1.y;
            }
            *(float2*)o0 = make_float2(v0, v1);
            *(float2*)o1 = make_float2(v2, v3);
        }
        __syncthreads();
    }
}

// ---------------- probs = sigmoid(max_l scores) * mask (tf32-clean) + transpose ----------------
__global__ void probs_kernel(const float* __restrict__ scores,
                             const float* __restrict__ mask,
                             float* __restrict__ probsAll)
{
    int i = blockIdx.x, b = blockIdx.y;
    for (int j = threadIdx.x; j < K_; j += blockDim.x) {
        const float* s = scores + (((long)(b * K_ + i)) * K_ + j) * L_;
        float m = s[0];
        #pragma unroll
        for (int c = 1; c < L_; c++) m = fmaxf(m, s[c]);
        float p = rna((1.f / (1.f + expf(-m))) * mask[((long)(b * K_ + i)) * K_ + j]);
        probsAll[((long)(b * K_ + i)) * K_ + j] = p;
        probsAll[(long)SZ_P + ((long)(b * K_ + j)) * K_ + i] = p;
    }
}

// ---------------- inverse row sums over probsAll (2*B*K rows) ----------------
__global__ void invsum_kernel(const float* __restrict__ probsAll,
                              float* __restrict__ invAll)
{
    int row = blockIdx.x;
    const float* src = probsAll + (long)row * K_;
    float s = 0.f;
    for (int j = threadIdx.x; j < K_; j += blockDim.x) s += src[j];
    __shared__ float red[4];
    #pragma unroll
    for (int o = 16; o > 0; o >>= 1) s += __shfl_down_sync(0xffffffffu, s, o);
    int wid = threadIdx.x >> 5;
    if ((threadIdx.x & 31) == 0) red[wid] = s;
    __syncthreads();
    if (threadIdx.x == 0) {
        s = red[0] + red[1] + red[2] + red[3];
        invAll[row] = 1.f / (s + 1e-7f);
    }
}

// ---------------- scatter with last-write-wins semantics ----------------
__global__ void scatter_kernel(const float* __restrict__ u,
                               const float* __restrict__ all_span,
                               const int* __restrict__ prune,
                               const int* __restrict__ span_len,
                               float* __restrict__ out_all)
{
    int bk = blockIdx.x;
    int b = bk / K_, k = bk % K_;
    int idx = prune[bk];
    bool last = (k == K_ - 1) || (prune[bk + 1] != idx);
    if (!last) return;
    bool valid = k < span_len[b];
    const float* src = valid ? (u + (long)bk * D_)
                             : (all_span + ((long)b * N_ + idx) * D_);
    float* dst = out_all + ((long)b * N_ + idx) * D_;
    int t = threadIdx.x;
    float4 v = *(const float4*)(src + t * 4);
    *(float4*)(dst + t * 4) = v;
}

// ---------------- host orchestration ----------------
extern "C" void kernel_launch(void* const* d_in, const int* in_sizes, int n_in,
                              void* d_out, int out_size)
{
    const float* span_vecs  = (const float*)d_in[0];
    const float* all_span   = (const float*)d_in[1];
    const int*   span_begin = (const int*)  d_in[2];
    const int*   span_end   = (const int*)  d_in[3];
    const float* mask       = (const float*)d_in[4];
    const int*   prune      = (const int*)  d_in[5];
    const int*   span_len   = (const int*)  d_in[6];
    const float* Wl  = (const float*)d_in[8];
    const float* bl  = (const float*)d_in[9];
    const float* Wr  = (const float*)d_in[10];
    const float* br  = (const float*)d_in[11];
    const float* de  = (const float*)d_in[12];
    const float* Wd  = (const float*)d_in[13];
    const float* bd  = (const float*)d_in[14];
    const float* Wo  = (const float*)d_in[15];
    const float* bo  = (const float*)d_in[16];
    const float* Wff1= (const float*)d_in[17];
    const float* Wff2= (const float*)d_in[18];
    const float* Wg  = (const float*)d_in[19];
    const float* bg  = (const float*)d_in[20];

    float *u, *u2, *ut, *ut2, *lr, *wlr, *blr, *dp, *probsAll, *invAll, *c, *tmp, *ctxt;
    float *wff1t, *wff2t, *wgt;
    cudaGetSymbolAddress((void**)&u,        g_u);
    cudaGetSymbolAddress((void**)&u2,       g_u2);
    cudaGetSymbolAddress((void**)&ut,       g_ut);
    cudaGetSymbolAddress((void**)&ut2,      g_ut2);
    cudaGetSymbolAddress((void**)&lr,       g_lr);
    cudaGetSymbolAddress((void**)&wlr,      g_wlr);
    cudaGetSymbolAddress((void**)&blr,      g_blr);
    cudaGetSymbolAddress((void**)&dp,       g_dp);
    cudaGetSymbolAddress((void**)&probsAll, g_probs);
    cudaGetSymbolAddress((void**)&invAll,   g_inv);
    cudaGetSymbolAddress((void**)&c,        g_c);
    cudaGetSymbolAddress((void**)&tmp,      g_tmp);
    cudaGetSymbolAddress((void**)&ctxt,     g_ctxt);
    cudaGetSymbolAddress((void**)&wff1t,    g_wff1t);
    cudaGetSymbolAddress((void**)&wff2t,    g_wff2t);
    cudaGetSymbolAddress((void**)&wgt,      g_wgt);

    float* out_all = (float*)d_out;
    float* out_u   = out_all + (size_t)B_ * N_ * D_;
    float* out_sc  = out_u   + (size_t)B_ * K_ * D_;

    const int M = B_ * K_;  // 768

    const int smem64 = 3 * (64 * ASTRIDE + 32 * BSTRIDE) * 4;  // 55296
    const int smem32 = 3 * (32 * ASTRIDE + 32 * BSTRIDE) * 4;  // 41472
    cudaFuncSetAttribute(mma_gemm<64>, cudaFuncAttributeMaxDynamicSharedMemorySize, smem64);

    convert_kernel<<<148, 256>>>(Wff1, Wff2, Wg, span_vecs, wff1t, wff2t, wgt, u, ut);
    init_kernel<<<128, 256>>>(de, Wd, bd, Wl, bl, Wr, br, dp, wlr, blr);

    float *ucur = u,  *unext = u2;
    float *utcur = ut, *utnext = ut2;

    // initial l|r projection + scorer
    mma_gemm<32><<<dim3(6, 24, 1), 128, smem32>>>(utcur, utcur, utcur, wlr, blr, nullptr, nullptr, nullptr,
                                                  lr, nullptr, M, LRWP_, D_, D_, LRWP_, 0, 0, 0, 0, 0, 0, 0);
    scorer_tc<<<dim3(K_, B_), 128>>>(lr, dp, Wo, bo, span_begin, span_end, out_sc, 1);

    for (int it = 0; it < 2; it++) {
        probs_kernel<<<dim3(K_, B_), 128>>>(out_sc, mask, probsAll);
        invsum_kernel<<<2 * B_ * K_, 128>>>(probsAll, invAll);

        // c[z] = (probsAll[z] @ ut[z&1]) * invAll[z]  (tf32-clean out)
        mma_gemm<64><<<dim3(16, 6, 4), 128, smem64>>>(probsAll, probsAll, probsAll, utcur, nullptr, invAll,
                                                      nullptr, nullptr, c, nullptr,
                                                      K_, D_, K_, K_, D_,
                                                      (long)K_*K_, (long)K_*D_, 1, (long)K_*D_, K_, 0, 1);

        // tmp = tanh([ut|c1|c2] @ Wff1)  (tf32-clean out)
        mma_gemm<64><<<dim3(16, 12, 1), 128, smem64>>>(utcur, c, c + SZ_U, wff1t, nullptr, nullptr,
                                                       nullptr, nullptr, tmp, nullptr,
                                                       M, D_, 3 * D_, D_, D_, 0, 0, 0, 0, 0, 1, 1);
        // ctxt = tmp @ Wff2  (tf32-clean out)
        mma_gemm<64><<<dim3(16, 12, 1), 128, smem64>>>(tmp, tmp, tmp, wff2t, nullptr, nullptr,
                                                       nullptr, nullptr, ctxt, nullptr,
                                                       M, D_, D_, D_, D_, 0, 0, 0, 0, 0, 0, 1);
        // unext = g*u + (1-g)*ctxt (fp32), utnext = rna(unext)
        mma_gemm<64><<<dim3(16, 12, 1), 128, smem64>>>(utcur, ctxt, ctxt, wgt, bg, nullptr,
                                                       ucur, ctxt, unext, utnext,
                                                       M, D_, 2 * D_, D_, D_, 0, 0, 0, 0, 0, 3, 0);
        float* s1 = ucur; ucur = unext; unext = s1;
        float* s2 = utcur; utcur = utnext; utnext = s2;

        // re-project + scorer (residual accumulate)
        mma_gemm<32><<<dim3(6, 24, 1), 128, smem32>>>(utcur, utcur, utcur, wlr, blr, nullptr, nullptr, nullptr,
                                                      lr, nullptr, M, LRWP_, D_, D_, LRWP_, 0, 0, 0, 0, 0, 0, 0);
        scorer_tc<<<dim3(K_, B_), 128>>>(lr, dp, Wo, bo, span_begin, span_end, out_sc, 0);
    }

    // outputs: update_all, u, scores (scores already written in place)
    cudaMemcpyAsync(out_all, all_span, sizeof(float) * (size_t)B_ * N_ * D_, cudaMemcpyDeviceToDevice);
    scatter_kernel<<<B_ * K_, 256>>>(ucur, all_span, prune, span_len, out_all);
    cudaMemcpyAsync(out_u, ucur, sizeof(float) * SZ_U, cudaMemcpyDeviceToDevice);
}

// round 8
// speedup vs baseline: 1.0334x; 1.0334x over previous
#include <cuda_runtime.h>
#include <math.h>

// ---------------- problem constants ----------------
#define B_    2
#define K_    384
#define N_    4096
#define D_    1024
#define H_    150
#define HP_   152     // padded H
#define LRWP_ 384     // l|r concatenated row width, padded
#define L_    12
#define NB_   10
#define DE_   20

#define SZ_U   (B_*K_*D_)       // 786432
#define SZ_P   (B_*K_*K_)       // 294912
#define SZ_S   (B_*K_)          // 768

// ---------------- device scratch (static, no allocs) ----------------
__device__ float g_u[SZ_U];        // fp32 u (ping)
__device__ float g_u2[SZ_U];       // fp32 u (pong)
__device__ float g_ut[SZ_U];       // tf32-clean u (ping)
__device__ float g_ut2[SZ_U];      // tf32-clean u (pong)
__device__ float g_lr[B_*K_*LRWP_];
__device__ float g_wlr[D_*LRWP_];  // tf32-clean
__device__ float g_blr[LRWP_];
__device__ float g_dp[NB_*HP_];
__device__ float g_probs[2*SZ_P];  // tf32-clean [probs b0,b1 | probsT b0,b1]
__device__ float g_inv[2*SZ_S];
__device__ float g_c[2*SZ_U];      // tf32-clean [c1 b0,b1 | c2 b0,b1]
__device__ float g_tmp[SZ_U];      // tf32-clean
__device__ float g_ctxt[SZ_U];     // tf32-clean
__device__ float g_wff1t[3*D_*D_]; // tf32-clean weights
__device__ float g_wff2t[D_*D_];
__device__ float g_wgt[2*D_*D_];

__device__ __forceinline__ unsigned f2t(float x) {
    unsigned r;
    asm("cvt.rna.tf32.f32 %0, %1;" : "=r"(r) : "f"(x));
    return r;
}
__device__ __forceinline__ float rna(float x) { return __uint_as_float(f2t(x)); }

__device__ __forceinline__ void cpa16(void* s, const void* g) {
    unsigned sa = (unsigned)__cvta_generic_to_shared(s);
    asm volatile("cp.async.cg.shared.global [%0], [%1], 16;" :: "r"(sa), "l"(g));
}
__device__ __forceinline__ void cp_commit() { asm volatile("cp.async.commit_group;"); }
template<int Nw>
__device__ __forceinline__ void cp_wait() { asm volatile("cp.async.wait_group %0;" :: "n"(Nw)); }

// ---------------- weight/input tf32 conversion (once per launch) ----------------
__global__ void convert_kernel(const float* __restrict__ Wff1,
                               const float* __restrict__ Wff2,
                               const float* __restrict__ Wg,
                               const float* __restrict__ span_vecs,
                               float* __restrict__ wff1t,
                               float* __restrict__ wff2t,
                               float* __restrict__ wgt,
                               float* __restrict__ u,
                               float* __restrict__ ut)
{
    int tid = blockIdx.x * blockDim.x + threadIdx.x;
    int nthr = gridDim.x * blockDim.x;
    for (int i = tid; i < 3*D_*D_; i += nthr) wff1t[i] = rna(Wff1[i]);
    for (int i = tid; i < D_*D_;   i += nthr) wff2t[i] = rna(Wff2[i]);
    for (int i = tid; i < 2*D_*D_; i += nthr) wgt[i]   = rna(Wg[i]);
    for (int i = tid; i < SZ_U; i += nthr) {
        float v = span_vecs[i];
        u[i] = v;
        ut[i] = rna(v);
    }
}

// ---------------- init: dp table + W_lr / b_lr concat (tf32-clean) ----------------
__global__ void init_kernel(const float* __restrict__ dist_emb,
                            const float* __restrict__ Wd,
                            const float* __restrict__ bd,
                            const float* __restrict__ Wl,
                            const float* __restrict__ bl,
                            const float* __restrict__ Wr,
                            const float* __restrict__ br,
                            float* __restrict__ dp,
                            float* __restrict__ wlr,
                            float* __restrict__ blr)
{
    int tid = blockIdx.x * blockDim.x + threadIdx.x;
    int nthr = gridDim.x * blockDim.x;
    for (int idx = tid; idx < NB_*HP_; idx += nthr) {
        int n = idx / HP_, h = idx % HP_;
        float v = 0.f;
        if (h < H_) {
            v = bd[h];
            #pragma unroll
            for (int t = 0; t < DE_; t++)
                v += dist_emb[n * DE_ + t] * Wd[t * H_ + h];
        }
        dp[idx] = v;
    }
    for (int idx = tid; idx < D_*LRWP_; idx += nthr) {
        int k = idx / LRWP_, c = idx % LRWP_;
        float v = 0.f;
        if (c < H_) v = Wl[k * H_ + c];
        else if (c >= HP_ && c < HP_ + H_) v = Wr[k * H_ + (c - HP_)];
        wlr[idx] = rna(v);
    }
    for (int c = tid; c < LRWP_; c += nthr) {
        float v = 0.f;
        if (c < H_) v = bl[c];
        else if (c >= HP_ && c < HP_ + H_) v = br[c - HP_];
        blr[c] = v;
    }
}

// ---------------- tf32 tensor-core GEMM, cp.async 3-stage, single sync/tile ----------------
#define ASTRIDE 36
#define BSTRIDE 72
template<int BM>
__global__ void __launch_bounds__(128, 2)
mma_gemm(const float* __restrict__ a0,
         const float* __restrict__ a1,
         const float* __restrict__ a2,
         const float* __restrict__ W,
         const float* __restrict__ bias,
         const float* __restrict__ rowscale,
         const float* __restrict__ e1,
         const float* __restrict__ e2,
         float* __restrict__ Cout,
         float* __restrict__ Ct,
         int M, int N, int K, int lda, int ldc,
         long sA, long sW, int bzmask, long sC, int sRS,
         int act, int roundOut)
{
    constexpr int MT = BM / 32;
    constexpr int ACH = (BM == 64) ? 4 : 2;
    constexpr int ASZ = BM * ASTRIDE;
    constexpr int BSZ = 32 * BSTRIDE;
    extern __shared__ unsigned dsm[];
    unsigned* Abase = dsm;
    unsigned* Bbase = dsm + 3 * ASZ;

    int z = blockIdx.z;
    a0 += (long)z * sA;
    W  += (long)(z & bzmask) * sW;
    Cout += (long)z * sC;
    if (rowscale) rowscale += (long)z * sRS;

    int tid = threadIdx.x;
    int warp = tid >> 5, lane = tid & 31;
    int m0 = blockIdx.y * BM, n0 = blockIdx.x * 64;
    int wm = (warp >> 1) * (BM / 2), wn = (warp & 1) * 32;

    auto issue = [&](int k0, int stage) {
        unsigned* As = Abase + stage * ASZ;
        unsigned* Bs = Bbase + stage * BSZ;
        int seg = k0 >> 10, col = k0 & 1023;
        const float* ap = (seg == 0) ? a0 : (seg == 1) ? a1 : a2;
        #pragma unroll
        for (int i = 0; i < ACH; i++) {
            int id = tid + i * 128;
            int row = id >> 3, c16 = (id & 7) * 4;
            cpa16(As + row * ASTRIDE + c16, ap + (long)(m0 + row) * lda + col + c16);
        }
        #pragma unroll
        for (int i = 0; i < 4; i++) {
            int id = tid + i * 128;
            int kr = id >> 4, c16 = (id & 15) * 4;
            cpa16(Bs + kr * BSTRIDE + c16, W + (long)(k0 + kr) * N + n0 + c16);
        }
        cp_commit();
    };

    int nt = K >> 5;
    issue(0, 0);
    issue(32, 1);

    float acc[MT][4][4];
    #pragma unroll
    for (int i = 0; i < MT; i++)
        #pragma unroll
        for (int j = 0; j < 4; j++)
            #pragma unroll
            for (int q = 0; q < 4; q++) acc[i][j][q] = 0.f;

    int stage = 0;
    for (int t = 0; t < nt; t++) {
        if (t == nt - 1) cp_wait<0>(); else cp_wait<1>();
        __syncthreads();
        if (t + 2 < nt) issue((t + 2) << 5, (stage + 2) % 3);

        unsigned* As = Abase + stage * ASZ;
        unsigned* Bs = Bbase + stage * BSZ;

        #pragma unroll
        for (int kx = 0; kx < 4; kx++) {
            unsigned a[MT][4];
            #pragma unroll
            for (int mt = 0; mt < MT; mt++) {
                int r_ = wm + mt * 16 + (lane >> 2);
                int c_ = kx * 8 + (lane & 3);
                a[mt][0] = As[r_ * ASTRIDE + c_];
                a[mt][1] = As[(r_ + 8) * ASTRIDE + c_];
                a[mt][2] = As[r_ * ASTRIDE + c_ + 4];
                a[mt][3] = As[(r_ + 8) * ASTRIDE + c_ + 4];
            }
            #pragma unroll
            for (int ct = 0; ct < 4; ct++) {
                unsigned b0 = Bs[(kx*8 + (lane & 3)) * BSTRIDE + wn + ct*8 + (lane >> 2)];
                unsigned b1 = Bs[(kx*8 + (lane & 3) + 4) * BSTRIDE + wn + ct*8 + (lane >> 2)];
                #pragma unroll
                for (int mt = 0; mt < MT; mt++) {
                    asm volatile(
                        "mma.sync.aligned.m16n8k8.row.col.f32.tf32.tf32.f32 "
                        "{%0,%1,%2,%3}, {%4,%5,%6,%7}, {%8,%9}, {%0,%1,%2,%3};"
                        : "+f"(acc[mt][ct][0]), "+f"(acc[mt][ct][1]),
                          "+f"(acc[mt][ct][2]), "+f"(acc[mt][ct][3])
                        : "r"(a[mt][0]), "r"(a[mt][1]), "r"(a[mt][2]), "r"(a[mt][3]),
                          "r"(b0), "r"(b1));
                }
            }
        }
        stage = (stage + 1) % 3;
    }

    #pragma unroll
    for (int mt = 0; mt < MT; mt++) {
        #pragma unroll
        for (int rh = 0; rh < 2; rh++) {
            int gm = m0 + wm + mt * 16 + (lane >> 2) + rh * 8;
            float rs = rowscale ? rowscale[gm] : 1.f;
            #pragma unroll
            for (int ct = 0; ct < 4; ct++) {
                int gn = n0 + wn + ct * 8 + (lane & 3) * 2;
                float v0 = acc[mt][ct][rh * 2 + 0];
                float v1 = acc[mt][ct][rh * 2 + 1];
                if (bias) { v0 += bias[gn]; v1 += bias[gn + 1]; }
                v0 *= rs; v1 *= rs;
                long off = (long)gm * ldc + gn;
                if (act == 1) { v0 = tanhf(v0); v1 = tanhf(v1); }
                else if (act == 2) {
                    v0 = 1.f / (1.f + expf(-v0));
                    v1 = 1.f / (1.f + expf(-v1));
                }
                else if (act == 3) {
                    float g0 = 1.f / (1.f + expf(-v0));
                    float g1 = 1.f / (1.f + expf(-v1));
                    v0 = g0 * e1[off]     + (1.f - g0) * e2[off];
                    v1 = g1 * e1[off + 1] + (1.f - g1) * e2[off + 1];
                }
                if (roundOut) { v0 = rna(v0); v1 = rna(v1); }
                *(float2*)(Cout + off) = make_float2(v0, v1);
                if (Ct) *(float2*)(Ct + off) = make_float2(rna(v0), rna(v1));
            }
        }
    }
}

// ---------------- tensor-core pairwise scorer v3: warp-private tiles ----------------
// Block (i,b), 256 threads = 8 warps. Each warp owns 3 j-tiles of 16 and a
// private 16x152 H region (stride 156). Only __syncwarp in the main loop.
// K = 152 = 19 k-steps of 8. N = 16 (12 used) via 2 n-tiles of m16n8k8.
#define SCOR_HSTRIDE 156
#define SCOR_SMEM_WORDS (NB_*HP_ + 2*1216 + K_ + 16 + 8*16*SCOR_HSTRIDE)
__global__ void __launch_bounds__(256)
scorer_tc(const float* __restrict__ lr,
          const float* __restrict__ dp,
          const float* __restrict__ Wo,
          const float* __restrict__ bo,
          const int* __restrict__ span_begin,
          const int* __restrict__ span_end,
          float* __restrict__ scores,
          int first)
{
    extern __shared__ float sm[];
    float*    s_t  = sm;                            // [NB][152]
    unsigned* s_w0 = (unsigned*)(sm + NB_*HP_);     // [2][19][32]
    unsigned* s_w1 = s_w0 + 1216;                   // [2][19][32]
    int*      s_bk = (int*)(s_w1 + 1216);           // [384]
    float*    s_bo = (float*)(s_bk + K_);           // [16]
    float*    s_h  = s_bo + 16;                     // [8][16][156]

    int i = blockIdx.x, b = blockIdx.y;
    int tid = threadIdx.x;
    int warp = tid >> 5, lane = tid & 31;

    // t[n][h] = rna(l_i[h] + dp[n][h])
    const float* lrow = lr + (long)(b * K_ + i) * LRWP_;
    for (int x = tid; x < NB_ * HP_; x += 256)
        s_t[x] = rna(lrow[x % HP_] + dp[x]);

    // Wo fragment tables: value(k,n) with k = kt*8+(ln&3) (+4 for w1), n = nt*8+(ln>>2)
    for (int x = tid; x < 2 * 19 * 32; x += 256) {
        int ln = x & 31, kt = (x >> 5) % 19, nt = x / (19 * 32);
        int k0 = kt * 8 + (ln & 3), k1 = k0 + 4;
        int n  = nt * 8 + (ln >> 2);
        s_w0[x] = (k0 < H_ && n < L_) ? f2t(Wo[k0 * L_ + n]) : 0u;
        s_w1[x] = (k1 < H_ && n < L_) ? f2t(Wo[k1 * L_ + n]) : 0u;
    }

    int endi = span_end[b * K_ + i];
    for (int j = tid; j < K_; j += 256) {
        int d = span_begin[b * K_ + j] - endi;
        int da = d < 0 ? -d : d;
        int bk;
        if (da <= 4) bk = da;
        else {
            int lg = 31 - __clz(da) + 3;
            bk = lg < (NB_ - 1) ? lg : (NB_ - 1);
        }
        s_bk[j] = bk;
    }
    if (tid < 16) s_bo[tid] = (tid < L_) ? bo[tid] : 0.f;
    __syncthreads();

    float* hbase = s_h + warp * (16 * SCOR_HSTRIDE);
    const float* rbase = lr + (long)b * K_ * LRWP_ + HP_;
    int row = lane >> 1, half = lane & 1;   // build mapping
    int ar = lane >> 2, ac = lane & 3;      // frag mapping
    long srow = (long)(b * K_ + i) * K_;

    #pragma unroll
    for (int s = 0; s < 3; s++) {
        int j0 = (s * 8 + warp) * 16;

        // build private H tile: H[row][h] = rna(relu(t[bk][h] + r[j0+row][h]))
        {
            int j = j0 + row;
            const float* rr = rbase + (long)j * LRWP_ + half * 76;
            const float* tt = s_t + s_bk[j] * HP_ + half * 76;
            float* hh = hbase + row * SCOR_HSTRIDE + half * 76;
            #pragma unroll
            for (int x = 0; x < 19; x++) {
                float4 rv = *(const float4*)(rr + x * 4);
                float4 tv = *(const float4*)(tt + x * 4);
                float4 hv;
                hv.x = rna(fmaxf(rv.x + tv.x, 0.f));
                hv.y = rna(fmaxf(rv.y + tv.y, 0.f));
                hv.z = rna(fmaxf(rv.z + tv.z, 0.f));
                hv.w = rna(fmaxf(rv.w + tv.w, 0.f));
                *(float4*)(hh + x * 4) = hv;
            }
        }
        __syncwarp();

        float acc0[4] = {0.f, 0.f, 0.f, 0.f};
        float acc1[4] = {0.f, 0.f, 0.f, 0.f};
        #pragma unroll
        for (int kt = 0; kt < 19; kt++) {
            unsigned a0 = __float_as_uint(hbase[ar * SCOR_HSTRIDE + kt * 8 + ac]);
            unsigned a1 = __float_as_uint(hbase[(ar + 8) * SCOR_HSTRIDE + kt * 8 + ac]);
            unsigned a2 = __float_as_uint(hbase[ar * SCOR_HSTRIDE + kt * 8 + ac + 4]);
            unsigned a3 = __float_as_uint(hbase[(ar + 8) * SCOR_HSTRIDE + kt * 8 + ac + 4]);
            unsigned b00 = s_w0[kt * 32 + lane];
            unsigned b01 = s_w1[kt * 32 + lane];
            asm volatile(
                "mma.sync.aligned.m16n8k8.row.col.f32.tf32.tf32.f32 "
                "{%0,%1,%2,%3}, {%4,%5,%6,%7}, {%8,%9}, {%0,%1,%2,%3};"
                : "+f"(acc0[0]), "+f"(acc0[1]), "+f"(acc0[2]), "+f"(acc0[3])
                : "r"(a0), "r"(a1), "r"(a2), "r"(a3), "r"(b00), "r"(b01));
            unsigned b10 = s_w0[(19 + kt) * 32 + lane];
            unsigned b11 = s_w1[(19 + kt) * 32 + lane];
            asm volatile(
                "mma.sync.aligned.m16n8k8.row.col.f32.tf32.tf32.f32 "
                "{%0,%1,%2,%3}, {%4,%5,%6,%7}, {%8,%9}, {%0,%1,%2,%3};"
                : "+f"(acc1[0]), "+f"(acc1[1]), "+f"(acc1[2]), "+f"(acc1[3])
                : "r"(a0), "r"(a1), "r"(a2), "r"(a3), "r"(b10), "r"(b11));
        }

        // epilogue (warp-private rows -> race-free)
        {
            int gc = (lane & 3) * 2;             // 0,2,4,6 < 12 always
            int gj = j0 + ar;
            long o = (srow + gj) * L_ + gc;
            float v0 = acc0[0] + s_bo[gc];
            float v1 = acc0[1] + s_bo[gc + 1];
            float v2 = acc0[2] + s_bo[gc];
            float v3 = acc0[3] + s_bo[gc + 1];
            float* p0 = scores + o;
            float* p1 = scores + o + 8 * L_;
            if (!first) {
                float2 q0 = *(float2*)p0, q1 = *(float2*)p1;
                v0 += q0.x; v1 += q0.y; v2 += q1.x; v3 += q1.y;
            }
            *(float2*)p0 = make_float2(v0, v1);
            *(float2*)p1 = make_float2(v2, v3);
        }
        {
            int gc = 8 + (lane & 3) * 2;         // 8,10,12,14 -> keep <12
            if (gc < L_) {
                int gj = j0 + ar;
                long o = (srow + gj) * L_ + gc;
                float v0 = acc1[0] + s_bo[gc];
                float v1 = acc1[1] + s_bo[gc + 1];
                float v2 = acc1[2] + s_bo[gc];
                float v3 = acc1[3] + s_bo[gc + 1];
                float* p0 = scores + o;
                float* p1 = scores + o + 8 * L_;
                if (!first) {
                    float2 q0 = *(float2*)p0, q1 = *(float2*)p1;
                    v0 += q0.x; v1 += q0.y; v2 += q1.x; v3 += q1.y;
                }
                *(float2*)p0 = make_float2(v0, v1);
                *(float2*)p1 = make_float2(v2, v3);
            }
        }
        __syncwarp();
    }
}

// ---------------- probs = sigmoid(max_l scores) * mask (tf32-clean) + transpose ----------------
__global__ void probs_kernel(const float* __restrict__ scores,
                             const float* __restrict__ mask,
                             float* __restrict__ probsAll)
{
    int i = blockIdx.x, b = blockIdx.y;
    for (int j = threadIdx.x; j < K_; j += blockDim.x) {
        const float* s = scores + (((long)(b * K_ + i)) * K_ + j) * L_;
        float m = s[0];
        #pragma unroll
        for (int c = 1; c < L_; c++) m = fmaxf(m, s[c]);
        float p = rna((1.f / (1.f + expf(-m))) * mask[((long)(b * K_ + i)) * K_ + j]);
        probsAll[((long)(b * K_ + i)) * K_ + j] = p;
        probsAll[(long)SZ_P + ((long)(b * K_ + j)) * K_ + i] = p;
    }
}

// ---------------- inverse row sums over probsAll (2*B*K rows) ----------------
__global__ void invsum_kernel(const float* __restrict__ probsAll,
                              float* __restrict__ invAll)
{
    int row = blockIdx.x;
    const float* src = probsAll + (long)row * K_;
    float s = 0.f;
    for (int j = threadIdx.x; j < K_; j += blockDim.x) s += src[j];
    __shared__ float red[4];
    #pragma unroll
    for (int o = 16; o > 0; o >>= 1) s += __shfl_down_sync(0xffffffffu, s, o);
    int wid = threadIdx.x >> 5;
    if ((threadIdx.x & 31) == 0) red[wid] = s;
    __syncthreads();
    if (threadIdx.x == 0) {
        s = red[0] + red[1] + red[2] + red[3];
        invAll[row] = 1.f / (s + 1e-7f);
    }
}

// ---------------- scatter with last-write-wins semantics ----------------
__global__ void scatter_kernel(const float* __restrict__ u,
                               const float* __restrict__ all_span,
                               const int* __restrict__ prune,
                               const int* __restrict__ span_len,
                               float* __restrict__ out_all)
{
    int bk = blockIdx.x;
    int b = bk / K_, k = bk % K_;
    int idx = prune[bk];
    bool last = (k == K_ - 1) || (prune[bk + 1] != idx);
    if (!last) return;
    bool valid = k < span_len[b];
    const float* src = valid ? (u + (long)bk * D_)
                             : (all_span + ((long)b * N_ + idx) * D_);
    float* dst = out_all + ((long)b * N_ + idx) * D_;
    int t = threadIdx.x;
    float4 v = *(const float4*)(src + t * 4);
    *(float4*)(dst + t * 4) = v;
}

// ---------------- host orchestration ----------------
extern "C" void kernel_launch(void* const* d_in, const int* in_sizes, int n_in,
                              void* d_out, int out_size)
{
    const float* span_vecs  = (const float*)d_in[0];
    const float* all_span   = (const float*)d_in[1];
    const int*   span_begin = (const int*)  d_in[2];
    const int*   span_end   = (const int*)  d_in[3];
    const float* mask       = (const float*)d_in[4];
    const int*   prune      = (const int*)  d_in[5];
    const int*   span_len   = (const int*)  d_in[6];
    const float* Wl  = (const float*)d_in[8];
    const float* bl  = (const float*)d_in[9];
    const float* Wr  = (const float*)d_in[10];
    const float* br  = (const float*)d_in[11];
    const float* de  = (const float*)d_in[12];
    const float* Wd  = (const float*)d_in[13];
    const float* bd  = (const float*)d_in[14];
    const float* Wo  = (const float*)d_in[15];
    const float* bo  = (const float*)d_in[16];
    const float* Wff1= (const float*)d_in[17];
    const float* Wff2= (const float*)d_in[18];
    const float* Wg  = (const float*)d_in[19];
    const float* bg  = (const float*)d_in[20];

    float *u, *u2, *ut, *ut2, *lr, *wlr, *blr, *dp, *probsAll, *invAll, *c, *tmp, *ctxt;
    float *wff1t, *wff2t, *wgt;
    cudaGetSymbolAddress((void**)&u,        g_u);
    cudaGetSymbolAddress((void**)&u2,       g_u2);
    cudaGetSymbolAddress((void**)&ut,       g_ut);
    cudaGetSymbolAddress((void**)&ut2,      g_ut2);
    cudaGetSymbolAddress((void**)&lr,       g_lr);
    cudaGetSymbolAddress((void**)&wlr,      g_wlr);
    cudaGetSymbolAddress((void**)&blr,      g_blr);
    cudaGetSymbolAddress((void**)&dp,       g_dp);
    cudaGetSymbolAddress((void**)&probsAll, g_probs);
    cudaGetSymbolAddress((void**)&invAll,   g_inv);
    cudaGetSymbolAddress((void**)&c,        g_c);
    cudaGetSymbolAddress((void**)&tmp,      g_tmp);
    cudaGetSymbolAddress((void**)&ctxt,     g_ctxt);
    cudaGetSymbolAddress((void**)&wff1t,    g_wff1t);
    cudaGetSymbolAddress((void**)&wff2t,    g_wff2t);
    cudaGetSymbolAddress((void**)&wgt,      g_wgt);

    float* out_all = (float*)d_out;
    float* out_u   = out_all + (size_t)B_ * N_ * D_;
    float* out_sc  = out_u   + (size_t)B_ * K_ * D_;

    const int M = B_ * K_;  // 768

    const int smem64 = 3 * (64 * ASTRIDE + 32 * BSTRIDE) * 4;  // 55296
    const int smem32 = 3 * (32 * ASTRIDE + 32 * BSTRIDE) * 4;  // 41472
    const int smemSc = SCOR_SMEM_WORDS * 4;                    // ~97KB
    cudaFuncSetAttribute(mma_gemm<64>, cudaFuncAttributeMaxDynamicSharedMemorySize, smem64);
    cudaFuncSetAttribute(scorer_tc, cudaFuncAttributeMaxDynamicSharedMemorySize, smemSc);

    convert_kernel<<<148, 256>>>(Wff1, Wff2, Wg, span_vecs, wff1t, wff2t, wgt, u, ut);
    init_kernel<<<128, 256>>>(de, Wd, bd, Wl, bl, Wr, br, dp, wlr, blr);

    float *ucur = u,  *unext = u2;
    float *utcur = ut, *utnext = ut2;

    // initial l|r projection + scorer
    mma_gemm<32><<<dim3(6, 24, 1), 128, smem32>>>(utcur, utcur, utcur, wlr, blr, nullptr, nullptr, nullptr,
                                                  lr, nullptr, M, LRWP_, D_, D_, LRWP_, 0, 0, 0, 0, 0, 0, 0);
    scorer_tc<<<dim3(K_, B_), 256, smemSc>>>(lr, dp, Wo, bo, span_begin, span_end, out_sc, 1);

    for (int it = 0; it < 2; it++) {
        probs_kernel<<<dim3(K_, B_), 128>>>(out_sc, mask, probsAll);
        invsum_kernel<<<2 * B_ * K_, 128>>>(probsAll, invAll);

        // c[z] = (probsAll[z] @ ut[z&1]) * invAll[z]  (tf32-clean out)
        mma_gemm<64><<<dim3(16, 6, 4), 128, smem64>>>(probsAll, probsAll, probsAll, utcur, nullptr, invAll,
                                                      nullptr, nullptr, c, nullptr,
                                                      K_, D_, K_, K_, D_,
                                                      (long)K_*K_, (long)K_*D_, 1, (long)K_*D_, K_, 0, 1);

        // tmp = tanh([ut|c1|c2] @ Wff1)  (tf32-clean out)
        mma_gemm<64><<<dim3(16, 12, 1), 128, smem64>>>(utcur, c, c + SZ_U, wff1t, nullptr, nullptr,
                                                       nullptr, nullptr, tmp, nullptr,
                                                       M, D_, 3 * D_, D_, D_, 0, 0, 0, 0, 0, 1, 1);
        // ctxt = tmp @ Wff2  (tf32-clean out)
        mma_gemm<64><<<dim3(16, 12, 1), 128, smem64>>>(tmp, tmp, tmp, wff2t, nullptr, nullptr,
                                                       nullptr, nullptr, ctxt, nullptr,
                                                       M, D_, D_, D_, D_, 0, 0, 0, 0, 0, 0, 1);
        // unext = g*u + (1-g)*ctxt (fp32), utnext = rna(unext)
        mma_gemm<64><<<dim3(16, 12, 1), 128, smem64>>>(utcur, ctxt, ctxt, wgt, bg, nullptr,
                                                       ucur, ctxt, unext, utnext,
                                                       M, D_, 2 * D_, D_, D_, 0, 0, 0, 0, 0, 3, 0);
        float* s1 = ucur; ucur = unext; unext = s1;
        float* s2 = utcur; utcur = utnext; utnext = s2;

        // re-project + scorer (residual accumulate)
        mma_gemm<32><<<dim3(6, 24, 1), 128, smem32>>>(utcur, utcur, utcur, wlr, blr, nullptr, nullptr, nullptr,
                                                      lr, nullptr, M, LRWP_, D_, D_, LRWP_, 0, 0, 0, 0, 0, 0, 0);
        scorer_tc<<<dim3(K_, B_), 256, smemSc>>>(lr, dp, Wo, bo, span_begin, span_end, out_sc, 0);
    }

    // outputs: update_all, u, scores (scores already written in place)
    cudaMemcpyAsync(out_all, all_span, sizeof(float) * (size_t)B_ * N_ * D_, cudaMemcpyDeviceToDevice);
    scatter_kernel<<<B_ * K_, 256>>>(ucur, all_span, prune, span_len, out_all);
    cudaMemcpyAsync(out_u, ucur, sizeof(float) * SZ_U, cudaMemcpyDeviceToDevice);
}